// round 3
// baseline (speedup 1.0000x reference)
#include <cuda_runtime.h>
#include <cuda_bf16.h>
#include <math_constants.h>

// Problem constants (fixed by setup_inputs)
#define Bq 4
#define Hq 8
#define BH 32          // B*H
#define Lq 2048
#define Dq 64
#define SK 40          // sample_k
#define NT 40          // n_top
#define SCALE 0.125f   // 1/sqrt(64)

#define TQ 256         // queries per block in k_M
#define KT 256         // keys per smem tile in k_M
#define NTILE (Lq / KT)

// ---------------- scratch (device globals; no allocation) ----------------
__device__ float g_M[BH * Lq];                 // 256 KB
__device__ int   g_top[BH * NT];               // 5 KB
__device__ float g_vmean[BH * Dq];             // 8 KB
__device__ float g_scores[(size_t)BH * NT * Lq];   // 10.5 MB
__device__ float g_part[8 * BH * NT * Dq];     // 2.6 MB (k-split partials)

// ---------------- kernel 1: M[bh,l] = max_s q.k - sum_s/L (smem tiled) ---
// Block = (bh, 256-query tile). Queries + indices staged once in smem;
// keys streamed through smem in 8 tiles of 256 rows. Each warp owns 32
// queries (lane j owns query w*32+j's accumulators). Per (query, tile):
// ballot the 40 sample indices against the tile, dot each hit from smem.
extern __shared__ float smem_dyn[];
__global__ void k_M_tiled(const float* __restrict__ Q,
                          const float* __restrict__ K,
                          const int* __restrict__ idxs) {
    float* sq   = smem_dyn;                    // TQ*64 floats (64 KB)
    float* skey = sq + TQ * Dq;                // KT*64 floats (64 KB)
    int*   sidx = (int*)(skey + KT * Dq);      // TQ*SK ints  (40 KB)

    int bh   = blockIdx.x >> 3;
    int qblk = blockIdx.x & 7;
    int t    = threadIdx.x;                    // 256 threads
    int lane = t & 31, w = t >> 5;
    int q0   = qblk * TQ;
    const float* Qb = Q + ((size_t)bh * Lq + q0) * Dq;
    const float* Kb = K + (size_t)bh * Lq * Dq;

    // stage queries (float4 coalesced) and indices
    {
        float4* sq4 = (float4*)sq;
        const float4* Qb4 = (const float4*)Qb;
        #pragma unroll
        for (int i = t; i < TQ * (Dq / 4); i += 256) sq4[i] = Qb4[i];
        for (int i = t; i < TQ * SK; i += 256) sidx[i] = idxs[q0 * SK + i];
    }

    float mx = -CUDART_INF_F, sm = 0.f;        // lane owns query w*32+lane

    for (int tile = 0; tile < NTILE; tile++) {
        __syncthreads();
        {
            float4* sk4 = (float4*)skey;
            const float4* Kt4 = (const float4*)(Kb + (size_t)tile * KT * Dq);
            #pragma unroll
            for (int i = t; i < KT * (Dq / 4); i += 256) sk4[i] = Kt4[i];
        }
        __syncthreads();

        for (int j = 0; j < 32; j++) {
            int qg = w * 32 + j;
            int i0 = sidx[qg * SK + lane];
            int i1 = (lane < 8) ? sidx[qg * SK + 32 + lane] : -1;
            unsigned m0 = __ballot_sync(0xffffffffu, (i0 >> 8) == tile);
            unsigned m1 = __ballot_sync(0xffffffffu, (i1 >> 8) == tile);
            if (!(m0 | m1)) continue;
            float2 qv = ((const float2*)(sq + qg * Dq))[lane];
            float lmx = -CUDART_INF_F, lsm = 0.f;
            while (m0) {
                int s = __ffs(m0) - 1; m0 &= m0 - 1;
                int idx = __shfl_sync(0xffffffffu, i0, s) & (KT - 1);
                float2 kv = ((const float2*)(skey + idx * Dq))[lane];
                float p = qv.x * kv.x + qv.y * kv.y;
                #pragma unroll
                for (int o = 16; o; o >>= 1) p += __shfl_xor_sync(0xffffffffu, p, o);
                lmx = fmaxf(lmx, p); lsm += p;
            }
            while (m1) {
                int s = __ffs(m1) - 1; m1 &= m1 - 1;
                int idx = __shfl_sync(0xffffffffu, i1, s) & (KT - 1);
                float2 kv = ((const float2*)(skey + idx * Dq))[lane];
                float p = qv.x * kv.x + qv.y * kv.y;
                #pragma unroll
                for (int o = 16; o; o >>= 1) p += __shfl_xor_sync(0xffffffffu, p, o);
                lmx = fmaxf(lmx, p); lsm += p;
            }
            if (lane == j) { mx = fmaxf(mx, lmx); sm += lsm; }
        }
    }
    g_M[(size_t)bh * Lq + q0 + w * 32 + lane] = mx - sm * (1.0f / (float)Lq);
}

// ---------------- kernel 2: top-40 per (b,h) (iterative argmax) ----------
__global__ void k_topk() {
    __shared__ float vals[Lq];
    __shared__ float wv[8];
    __shared__ int   wi[8];
    int bh = blockIdx.x;
    int t = threadIdx.x;
    for (int i = t; i < Lq; i += 256) vals[i] = g_M[bh * Lq + i];
    __syncthreads();
    int lane = t & 31, wid = t >> 5;
    for (int it = 0; it < NT; it++) {
        float bv = -CUDART_INF_F; int bi = Lq;
        for (int i = t; i < Lq; i += 256) {
            float v = vals[i];
            if (v > bv) { bv = v; bi = i; }
        }
        #pragma unroll
        for (int o = 16; o; o >>= 1) {
            float ov = __shfl_xor_sync(0xffffffffu, bv, o);
            int   oi = __shfl_xor_sync(0xffffffffu, bi, o);
            if (ov > bv || (ov == bv && oi < bi)) { bv = ov; bi = oi; }
        }
        if (lane == 0) { wv[wid] = bv; wi[wid] = bi; }
        __syncthreads();
        if (t == 0) {
            for (int wN = 1; wN < 8; wN++)
                if (wv[wN] > bv || (wv[wN] == bv && wi[wN] < bi)) { bv = wv[wN]; bi = wi[wN]; }
            g_top[bh * NT + it] = bi;
            vals[bi] = -CUDART_INF_F;
        }
        __syncthreads();
    }
}

// ---------------- kernel 3: V mean over L per (b,h), float4 --------------
__global__ void k_vmean(const float* __restrict__ V) {
    int bh = blockIdx.x;
    int t = threadIdx.x;               // 256
    int d4 = t & 15, part = t >> 4;    // 16 parts x 128 rows
    const float4* Vb = (const float4*)(V + (size_t)bh * Lq * Dq);
    float4 s = make_float4(0.f, 0.f, 0.f, 0.f);
    int k0 = part * 128;
    for (int k = k0; k < k0 + 128; k++) {
        float4 v = Vb[(size_t)k * 16 + d4];
        s.x += v.x; s.y += v.y; s.z += v.z; s.w += v.w;
    }
    __shared__ float4 ps[256];
    ps[t] = s;
    __syncthreads();
    if (t < 16) {
        float4 a = ps[t];
        #pragma unroll
        for (int pI = 1; pI < 16; pI++) {
            float4 v = ps[pI * 16 + t];
            a.x += v.x; a.y += v.y; a.z += v.z; a.w += v.w;
        }
        const float inv = 1.0f / (float)Lq;
        a.x *= inv; a.y *= inv; a.z *= inv; a.w *= inv;
        ((float4*)g_vmean)[bh * 16 + t] = a;
    }
}

// ---------------- kernel 4: broadcast V_mean (split into 4 launches) -----
__global__ void k_fill(float4* __restrict__ out4, int base) {
    int i = base + blockIdx.x * 256 + threadIdx.x;  // of BH*L*16 float4s
    int bh = i >> 15;
    int d4 = i & 15;
    out4[i] = ((const float4*)g_vmean)[bh * 16 + d4];
}

// ---------------- kernel 5: scores_top = (Q_top @ K^T) * scale -----------
__global__ void k_scores(const float* __restrict__ Q, const float* __restrict__ K) {
    __shared__ float qs[NT * Dq];           // 40x64
    __shared__ float Kt[Dq * 132];          // transposed [d][k], padded row 132
    int bh = blockIdx.x >> 4;
    int kt = blockIdx.x & 15;
    int t = threadIdx.x;
    const float* Qb = Q + (size_t)bh * Lq * Dq;
    const float* Kb = K + (size_t)bh * Lq * Dq;
    for (int j = t; j < NT * Dq; j += 256) {
        int u = j >> 6, d = j & 63;
        int qi = __ldg(&g_top[bh * NT + u]);
        qs[j] = Qb[(size_t)qi * Dq + d];
    }
    for (int j = t; j < 128 * Dq; j += 256) {
        int r = j >> 6, d = j & 63;
        Kt[d * 132 + r] = Kb[(size_t)(kt * 128 + r) * Dq + d];
    }
    __syncthreads();
    int tu = t >> 5;
    int tk = t & 31;
    float acc[5][4] = {};
    #pragma unroll 8
    for (int d = 0; d < Dq; d++) {
        float a[5];
        #pragma unroll
        for (int i = 0; i < 5; i++) a[i] = qs[(tu * 5 + i) * Dq + d];
        float4 b = *(const float4*)&Kt[d * 132 + tk * 4];
        #pragma unroll
        for (int i = 0; i < 5; i++) {
            acc[i][0] = fmaf(a[i], b.x, acc[i][0]);
            acc[i][1] = fmaf(a[i], b.y, acc[i][1]);
            acc[i][2] = fmaf(a[i], b.z, acc[i][2]);
            acc[i][3] = fmaf(a[i], b.w, acc[i][3]);
        }
    }
    #pragma unroll
    for (int i = 0; i < 5; i++) {
        int u = tu * 5 + i;
        float4 r;
        r.x = acc[i][0] * SCALE; r.y = acc[i][1] * SCALE;
        r.z = acc[i][2] * SCALE; r.w = acc[i][3] * SCALE;
        *(float4*)&g_scores[((size_t)(bh * NT + u)) * Lq + kt * 128 + tk * 4] = r;
    }
}

// ---------------- kernel 6: softmax over 2048 keys per top row -----------
__global__ void k_softmax() {
    __shared__ float red[8];
    int row = blockIdx.x;                  // BH*NT = 1280 rows
    float* s = g_scores + (size_t)row * Lq;
    int t = threadIdx.x, lane = t & 31, wid = t >> 5;
    float mx = -CUDART_INF_F;
    for (int i = t; i < Lq; i += 256) mx = fmaxf(mx, s[i]);
    #pragma unroll
    for (int o = 16; o; o >>= 1) mx = fmaxf(mx, __shfl_xor_sync(0xffffffffu, mx, o));
    if (lane == 0) red[wid] = mx;
    __syncthreads();
    mx = red[0];
    #pragma unroll
    for (int i = 1; i < 8; i++) mx = fmaxf(mx, red[i]);
    __syncthreads();
    float sum = 0.f;
    for (int i = t; i < Lq; i += 256) {
        float e = __expf(s[i] - mx);
        s[i] = e;
        sum += e;
    }
    #pragma unroll
    for (int o = 16; o; o >>= 1) sum += __shfl_xor_sync(0xffffffffu, sum, o);
    if (lane == 0) red[wid] = sum;
    __syncthreads();
    sum = 0.f;
    #pragma unroll
    for (int i = 0; i < 8; i++) sum += red[i];
    float inv = 1.0f / sum;
    for (int i = t; i < Lq; i += 256) s[i] *= inv;
}

// ---------------- kernel 7: ctx partial = attn @ V (k-split) -------------
__global__ void k_ctx(const float* __restrict__ V) {
    __shared__ float Vs[128 * Dq];          // 32 KB
    int bh = blockIdx.x >> 3;
    int ks = blockIdx.x & 7;
    int t = threadIdx.x;
    int tu = t >> 5;
    int td = t & 31;
    const float* Vb = V + (size_t)bh * Lq * Dq;
    const float* Sb = g_scores + (size_t)bh * NT * Lq;
    float acc[5][2] = {};
    for (int sub = 0; sub < 2; sub++) {
        int k0 = ks * 256 + sub * 128;
        __syncthreads();
        for (int j = t; j < 128 * Dq; j += 256) Vs[j] = Vb[(size_t)k0 * Dq + j];
        __syncthreads();
        #pragma unroll 4
        for (int kk = 0; kk < 128; kk++) {
            float a[5];
            #pragma unroll
            for (int i = 0; i < 5; i++)
                a[i] = __ldg(&Sb[(size_t)(tu * 5 + i) * Lq + k0 + kk]);
            float2 v = *(const float2*)&Vs[kk * Dq + td * 2];
            #pragma unroll
            for (int i = 0; i < 5; i++) {
                acc[i][0] = fmaf(a[i], v.x, acc[i][0]);
                acc[i][1] = fmaf(a[i], v.y, acc[i][1]);
            }
        }
    }
    #pragma unroll
    for (int i = 0; i < 5; i++) {
        int u = tu * 5 + i;
        float2 r; r.x = acc[i][0]; r.y = acc[i][1];
        *(float2*)&g_part[(((size_t)ks * BH + bh) * NT + u) * Dq + td * 2] = r;
    }
}

// ---------------- kernel 8: sum partials, scatter into output rows -------
__global__ void k_scatter(float* __restrict__ out) {
    int i = blockIdx.x * blockDim.x + threadIdx.x;   // BH*NT*D = 81920
    if (i >= BH * NT * Dq) return;
    int d = i & 63;
    int u = (i >> 6) % NT;
    int bh = (i >> 6) / NT;
    float s = 0.f;
    #pragma unroll
    for (int ks = 0; ks < 8; ks++)
        s += g_part[(((size_t)ks * BH + bh) * NT + u) * Dq + d];
    int qi = g_top[bh * NT + u];
    out[((size_t)bh * Lq + qi) * Dq + d] = s;
}

// ---------------- launch ---------------------------------------------------
extern "C" void kernel_launch(void* const* d_in, const int* in_sizes, int n_in,
                              void* d_out, int out_size) {
    const float* Q = (const float*)d_in[0];
    const float* K = (const float*)d_in[1];
    const float* V = (const float*)d_in[2];
    const int* idxs = (const int*)d_in[3];
    float* out = (float*)d_out;

    const int SMEM_KM = (TQ * Dq + KT * Dq) * 4 + TQ * SK * 4;  // 168 KB
    static int configured = 0;
    if (!configured) {
        cudaFuncSetAttribute(k_M_tiled, cudaFuncAttributeMaxDynamicSharedMemorySize, SMEM_KM);
        configured = 1;
    }

    // order chosen so k_M_tiled is the 6th launch (ncu -s 5 -c 1 captures it)
    k_vmean<<<BH, 256>>>(V);
    const int NF4 = BH * Lq * Dq / 4;            // 1048576 float4s
    k_fill<<<NF4 / 4 / 256, 256>>>((float4*)out, 0 * (NF4 / 4));
    k_fill<<<NF4 / 4 / 256, 256>>>((float4*)out, 1 * (NF4 / 4));
    k_fill<<<NF4 / 4 / 256, 256>>>((float4*)out, 2 * (NF4 / 4));
    k_fill<<<NF4 / 4 / 256, 256>>>((float4*)out, 3 * (NF4 / 4));
    k_M_tiled<<<BH * 8, 256, SMEM_KM>>>(Q, K, idxs);
    k_topk<<<BH, 256>>>();
    k_scores<<<BH * 16, 256>>>(Q, K);
    k_softmax<<<BH * NT, 256>>>();
    k_ctx<<<BH * 8, 256>>>(V);
    k_scatter<<<(BH * NT * Dq + 255) / 256, 256>>>(out);
}

// round 4
// speedup vs baseline: 3.1959x; 3.1959x over previous
#include <cuda_runtime.h>
#include <cuda_bf16.h>
#include <math_constants.h>

// Problem constants (fixed by setup_inputs)
#define Bq 4
#define Hq 8
#define BH 32          // B*H
#define Lq 2048
#define Dq 64
#define SK 40          // sample_k
#define NT 40          // n_top
#define SCALE 0.125f   // 1/sqrt(64)

// ---------------- scratch (device globals; no allocation) ----------------
__device__ float g_M[BH * Lq];                 // 256 KB
__device__ int   g_top[BH * NT];               // 5 KB
__device__ float g_vmean[BH * Dq];             // 8 KB
__device__ float g_scores[(size_t)BH * NT * Lq];   // 10.5 MB
__device__ float g_part[8 * BH * NT * Dq];     // 2.6 MB (k-split partials)

// ---------------- kernel 1: M[bh,l] = max_s q.k - sum_s/L ----------------
// Warp per query; 16 samples batched -> 16 independent LDG.64 in flight,
// butterfly reduction over the whole batch (shuffles pipeline).
template<int NB>
__device__ __forceinline__ void km_batch(const float* __restrict__ Kb,
                                         float2 q, int e0, int e1, int s0,
                                         int lane, float& mx, float& sm) {
    float p[NB];
    #pragma unroll
    for (int j = 0; j < NB; j++) {
        int s = s0 + j;
        int idx = (s < 32) ? __shfl_sync(0xffffffffu, e0, s)
                           : __shfl_sync(0xffffffffu, e1, s - 32);
        float2 k = ((const float2*)(Kb + (size_t)idx * Dq))[lane];
        p[j] = q.x * k.x + q.y * k.y;
    }
    #pragma unroll
    for (int o = 16; o; o >>= 1) {
        #pragma unroll
        for (int j = 0; j < NB; j++)
            p[j] += __shfl_xor_sync(0xffffffffu, p[j], o);
    }
    #pragma unroll
    for (int j = 0; j < NB; j++) { mx = fmaxf(mx, p[j]); sm += p[j]; }
}

__global__ void k_M(const float* __restrict__ Q, const float* __restrict__ K,
                    const int* __restrict__ idxs) {
    int w = blockIdx.x * 8 + (threadIdx.x >> 5);   // query id (bh*2048 + l)
    int lane = threadIdx.x & 31;
    int bh = w >> 11;
    int l  = w & (Lq - 1);
    float2 q = ((const float2*)(Q + (size_t)w * Dq))[lane];
    const float* Kb = K + (size_t)bh * Lq * Dq;
    int e0 = idxs[l * SK + lane];                       // s = lane
    int e1 = (lane < 8) ? idxs[l * SK + 32 + lane] : 0; // s = 32+lane
    float mx = -CUDART_INF_F;
    float sm = 0.f;
    km_batch<16>(Kb, q, e0, e1, 0,  lane, mx, sm);
    km_batch<16>(Kb, q, e0, e1, 16, lane, mx, sm);
    km_batch<8> (Kb, q, e0, e1, 32, lane, mx, sm);
    if (lane == 0) g_M[w] = mx - sm * (1.0f / (float)Lq);
}

// ---------------- kernel 2: top-40 per (b,h) (iterative argmax) ----------
__global__ void k_topk() {
    __shared__ float vals[Lq];
    __shared__ float wv[8];
    __shared__ int   wi[8];
    int bh = blockIdx.x;
    int t = threadIdx.x;
    for (int i = t; i < Lq; i += 256) vals[i] = g_M[bh * Lq + i];
    __syncthreads();
    int lane = t & 31, wid = t >> 5;
    for (int it = 0; it < NT; it++) {
        float bv = -CUDART_INF_F; int bi = Lq;
        for (int i = t; i < Lq; i += 256) {
            float v = vals[i];
            if (v > bv) { bv = v; bi = i; }
        }
        #pragma unroll
        for (int o = 16; o; o >>= 1) {
            float ov = __shfl_xor_sync(0xffffffffu, bv, o);
            int   oi = __shfl_xor_sync(0xffffffffu, bi, o);
            if (ov > bv || (ov == bv && oi < bi)) { bv = ov; bi = oi; }
        }
        if (lane == 0) { wv[wid] = bv; wi[wid] = bi; }
        __syncthreads();
        if (t == 0) {
            for (int wN = 1; wN < 8; wN++)
                if (wv[wN] > bv || (wv[wN] == bv && wi[wN] < bi)) { bv = wv[wN]; bi = wi[wN]; }
            g_top[bh * NT + it] = bi;
            vals[bi] = -CUDART_INF_F;
        }
        __syncthreads();
    }
}

// ---------------- kernel 3: V mean over L per (b,h), float4 --------------
__global__ void k_vmean(const float* __restrict__ V) {
    int bh = blockIdx.x;
    int t = threadIdx.x;               // 256
    int d4 = t & 15, part = t >> 4;    // 16 parts x 128 rows
    const float4* Vb = (const float4*)(V + (size_t)bh * Lq * Dq);
    float4 s = make_float4(0.f, 0.f, 0.f, 0.f);
    int k0 = part * 128;
    for (int k = k0; k < k0 + 128; k++) {
        float4 v = Vb[(size_t)k * 16 + d4];
        s.x += v.x; s.y += v.y; s.z += v.z; s.w += v.w;
    }
    __shared__ float4 ps[256];
    ps[t] = s;
    __syncthreads();
    if (t < 16) {
        float4 a = ps[t];
        #pragma unroll
        for (int pI = 1; pI < 16; pI++) {
            float4 v = ps[pI * 16 + t];
            a.x += v.x; a.y += v.y; a.z += v.z; a.w += v.w;
        }
        const float inv = 1.0f / (float)Lq;
        a.x *= inv; a.y *= inv; a.z *= inv; a.w *= inv;
        ((float4*)g_vmean)[bh * 16 + t] = a;
    }
}

// ---------------- kernel 4: broadcast V_mean (2 launches) ----------------
__global__ void k_fill(float4* __restrict__ out4, int base) {
    int i = base + blockIdx.x * 256 + threadIdx.x;  // of BH*L*16 float4s
    int bh = i >> 15;
    int d4 = i & 15;
    out4[i] = ((const float4*)g_vmean)[bh * 16 + d4];
}

// ---------------- kernel 5: scores_top = (Q_top @ K^T) * scale -----------
__global__ void k_scores(const float* __restrict__ Q, const float* __restrict__ K) {
    __shared__ float qs[NT * Dq];           // 40x64
    __shared__ float Kt[Dq * 132];          // transposed [d][k], padded row 132
    int bh = blockIdx.x >> 4;
    int kt = blockIdx.x & 15;
    int t = threadIdx.x;
    const float* Qb = Q + (size_t)bh * Lq * Dq;
    const float* Kb = K + (size_t)bh * Lq * Dq;
    for (int j = t; j < NT * Dq; j += 256) {
        int u = j >> 6, d = j & 63;
        int qi = __ldg(&g_top[bh * NT + u]);
        qs[j] = Qb[(size_t)qi * Dq + d];
    }
    for (int j = t; j < 128 * Dq; j += 256) {
        int r = j >> 6, d = j & 63;
        Kt[d * 132 + r] = Kb[(size_t)(kt * 128 + r) * Dq + d];
    }
    __syncthreads();
    int tu = t >> 5;
    int tk = t & 31;
    float acc[5][4] = {};
    #pragma unroll 8
    for (int d = 0; d < Dq; d++) {
        float a[5];
        #pragma unroll
        for (int i = 0; i < 5; i++) a[i] = qs[(tu * 5 + i) * Dq + d];
        float4 b = *(const float4*)&Kt[d * 132 + tk * 4];
        #pragma unroll
        for (int i = 0; i < 5; i++) {
            acc[i][0] = fmaf(a[i], b.x, acc[i][0]);
            acc[i][1] = fmaf(a[i], b.y, acc[i][1]);
            acc[i][2] = fmaf(a[i], b.z, acc[i][2]);
            acc[i][3] = fmaf(a[i], b.w, acc[i][3]);
        }
    }
    #pragma unroll
    for (int i = 0; i < 5; i++) {
        int u = tu * 5 + i;
        float4 r;
        r.x = acc[i][0] * SCALE; r.y = acc[i][1] * SCALE;
        r.z = acc[i][2] * SCALE; r.w = acc[i][3] * SCALE;
        *(float4*)&g_scores[((size_t)(bh * NT + u)) * Lq + kt * 128 + tk * 4] = r;
    }
}

// ---------------- kernel 6: softmax over 2048 keys per top row -----------
__global__ void k_softmax() {
    __shared__ float red[8];
    int row = blockIdx.x;                  // BH*NT = 1280 rows
    float* s = g_scores + (size_t)row * Lq;
    int t = threadIdx.x, lane = t & 31, wid = t >> 5;
    float mx = -CUDART_INF_F;
    for (int i = t; i < Lq; i += 256) mx = fmaxf(mx, s[i]);
    #pragma unroll
    for (int o = 16; o; o >>= 1) mx = fmaxf(mx, __shfl_xor_sync(0xffffffffu, mx, o));
    if (lane == 0) red[wid] = mx;
    __syncthreads();
    mx = red[0];
    #pragma unroll
    for (int i = 1; i < 8; i++) mx = fmaxf(mx, red[i]);
    __syncthreads();
    float sum = 0.f;
    for (int i = t; i < Lq; i += 256) {
        float e = __expf(s[i] - mx);
        s[i] = e;
        sum += e;
    }
    #pragma unroll
    for (int o = 16; o; o >>= 1) sum += __shfl_xor_sync(0xffffffffu, sum, o);
    if (lane == 0) red[wid] = sum;
    __syncthreads();
    sum = 0.f;
    #pragma unroll
    for (int i = 0; i < 8; i++) sum += red[i];
    float inv = 1.0f / sum;
    for (int i = t; i < Lq; i += 256) s[i] *= inv;
}

// ---------------- kernel 7: ctx partial = attn @ V (k-split) -------------
__global__ void k_ctx(const float* __restrict__ V) {
    __shared__ float Vs[128 * Dq];          // 32 KB
    int bh = blockIdx.x >> 3;
    int ks = blockIdx.x & 7;
    int t = threadIdx.x;
    int tu = t >> 5;
    int td = t & 31;
    const float* Vb = V + (size_t)bh * Lq * Dq;
    const float* Sb = g_scores + (size_t)bh * NT * Lq;
    float acc[5][2] = {};
    for (int sub = 0; sub < 2; sub++) {
        int k0 = ks * 256 + sub * 128;
        __syncthreads();
        for (int j = t; j < 128 * Dq; j += 256) Vs[j] = Vb[(size_t)k0 * Dq + j];
        __syncthreads();
        #pragma unroll 4
        for (int kk = 0; kk < 128; kk++) {
            float a[5];
            #pragma unroll
            for (int i = 0; i < 5; i++)
                a[i] = __ldg(&Sb[(size_t)(tu * 5 + i) * Lq + k0 + kk]);
            float2 v = *(const float2*)&Vs[kk * Dq + td * 2];
            #pragma unroll
            for (int i = 0; i < 5; i++) {
                acc[i][0] = fmaf(a[i], v.x, acc[i][0]);
                acc[i][1] = fmaf(a[i], v.y, acc[i][1]);
            }
        }
    }
    #pragma unroll
    for (int i = 0; i < 5; i++) {
        int u = tu * 5 + i;
        float2 r; r.x = acc[i][0]; r.y = acc[i][1];
        *(float2*)&g_part[(((size_t)ks * BH + bh) * NT + u) * Dq + td * 2] = r;
    }
}

// ---------------- kernel 8: sum partials, scatter into output rows -------
__global__ void k_scatter(float* __restrict__ out) {
    int i = blockIdx.x * blockDim.x + threadIdx.x;   // BH*NT*D = 81920
    if (i >= BH * NT * Dq) return;
    int d = i & 63;
    int u = (i >> 6) % NT;
    int bh = (i >> 6) / NT;
    float s = 0.f;
    #pragma unroll
    for (int ks = 0; ks < 8; ks++)
        s += g_part[(((size_t)ks * BH + bh) * NT + u) * Dq + d];
    int qi = g_top[bh * NT + u];
    out[((size_t)bh * Lq + qi) * Dq + d] = s;
}

// ---------------- launch ---------------------------------------------------
extern "C" void kernel_launch(void* const* d_in, const int* in_sizes, int n_in,
                              void* d_out, int out_size) {
    const float* Q = (const float*)d_in[0];
    const float* K = (const float*)d_in[1];
    const float* V = (const float*)d_in[2];
    const int* idxs = (const int*)d_in[3];
    float* out = (float*)d_out;

    // k_M is user launch #4 (profiler lands on user launch #4: 2 harness
    // pre-launches + "-s 5").
    const int NF4 = BH * Lq * Dq / 4;            // 1048576 float4s
    k_vmean<<<BH, 256>>>(V);                          // 1
    k_fill<<<NF4 / 2 / 256, 256>>>((float4*)out, 0);  // 2
    k_fill<<<NF4 / 2 / 256, 256>>>((float4*)out, NF4 / 2); // 3
    k_M<<<(BH * Lq) / 8, 256>>>(Q, K, idxs);          // 4  <-- profiled
    k_topk<<<BH, 256>>>();                            // 5
    k_scores<<<BH * 16, 256>>>(Q, K);                 // 6
    k_softmax<<<BH * NT, 256>>>();                    // 7
    k_ctx<<<BH * 8, 256>>>(V);                        // 8
    k_scatter<<<(BH * NT * Dq + 255) / 256, 256>>>(out); // 9
}

// round 5
// speedup vs baseline: 3.9495x; 1.2358x over previous
#include <cuda_runtime.h>
#include <cuda_bf16.h>
#include <math_constants.h>

// Problem constants (fixed by setup_inputs)
#define Bq 4
#define Hq 8
#define BH 32          // B*H
#define Lq 2048
#define Dq 64
#define SK 40          // sample_k
#define NT 40          // n_top
#define SCALE 0.125f   // 1/sqrt(64)

// ---------------- scratch (device globals; no allocation) ----------------
__device__ float g_M[BH * Lq];                 // 256 KB
__device__ int   g_top[BH * NT];               // 5 KB
__device__ float g_vmean[BH * Dq];             // 8 KB
__device__ float g_scores[(size_t)BH * NT * Lq];   // 10.5 MB
__device__ float g_part[8 * BH * NT * Dq];     // 2.6 MB (k-split partials)

// ---------------- kernel 1: M[bh,l] = max_s q.k - sum_s/L ----------------
// Warp per query. Dots computed lane-over-D (coalesced float2 gathers), then
// reduced with warp transpose-folds: V sample-arrays cost V-1 shuffles total
// instead of 5V butterfly shuffles.
template<int O, int V>
__device__ __forceinline__ void fold(float* p, int lane) {
    bool hi = (lane & O) != 0;
    #pragma unroll
    for (int j = 0; j < V / 2; j++) {
        float send = hi ? p[j] : p[j + V / 2];
        float keep = hi ? p[j + V / 2] : p[j];
        p[j] = keep + __shfl_xor_sync(0xffffffffu, send, O);
    }
}

// 16 sampled dots; returns full dot of sample (base + 8*b16+4*b8+2*b4+1*b2),
// replicated across lane-bit 1.
__device__ __forceinline__ float dot16(const float* __restrict__ Kb, float2 q,
                                       int e, int base, int lane) {
    float p[16];
    #pragma unroll
    for (int j = 0; j < 16; j++) {
        int idx = __shfl_sync(0xffffffffu, e, base + j);
        float2 k = ((const float2*)(Kb + (size_t)idx * Dq))[lane];
        p[j] = q.x * k.x + q.y * k.y;
    }
    fold<16, 16>(p, lane);
    fold<8, 8>(p, lane);
    fold<4, 4>(p, lane);
    fold<2, 2>(p, lane);
    p[0] += __shfl_xor_sync(0xffffffffu, p[0], 1);
    return p[0];
}

// 8 sampled dots; returns dot of sample (4*b16+2*b8+1*b4), replicated x4.
__device__ __forceinline__ float dot8(const float* __restrict__ Kb, float2 q,
                                      int e, int lane) {
    float p[8];
    #pragma unroll
    for (int j = 0; j < 8; j++) {
        int idx = __shfl_sync(0xffffffffu, e, j);
        float2 k = ((const float2*)(Kb + (size_t)idx * Dq))[lane];
        p[j] = q.x * k.x + q.y * k.y;
    }
    fold<16, 8>(p, lane);
    fold<8, 4>(p, lane);
    fold<4, 2>(p, lane);
    p[0] += __shfl_xor_sync(0xffffffffu, p[0], 2);
    p[0] += __shfl_xor_sync(0xffffffffu, p[0], 1);
    return p[0];
}

__global__ void k_M(const float* __restrict__ Q, const float* __restrict__ K,
                    const int* __restrict__ idxs) {
    int w = blockIdx.x * 8 + (threadIdx.x >> 5);   // query id (bh*2048 + l)
    int lane = threadIdx.x & 31;
    int bh = w >> 11;
    int l  = w & (Lq - 1);
    float2 q = ((const float2*)(Q + (size_t)w * Dq))[lane];
    const float* Kb = K + (size_t)bh * Lq * Dq;
    int e0 = idxs[l * SK + lane];                       // samples 0..31
    int e1 = (lane < 8) ? idxs[l * SK + 32 + lane] : 0; // samples 32..39

    float a = dot16(Kb, q, e0, 0, lane);   // each lane: one of dots 0..15
    float b = dot16(Kb, q, e0, 16, lane);  // one of dots 16..31
    float c = dot8(Kb, q, e1, lane);       // one of dots 32..39 (x4 replicated)

    float mx = fmaxf(fmaxf(a, b), c);
    float sm = 0.5f * (a + b) + 0.25f * c; // replication-exact weights
    #pragma unroll
    for (int o = 16; o; o >>= 1) {
        mx = fmaxf(mx, __shfl_xor_sync(0xffffffffu, mx, o));
        sm += __shfl_xor_sync(0xffffffffu, sm, o);
    }
    if (lane == 0) g_M[w] = mx - sm * (1.0f / (float)Lq);
}

// ---------------- kernel 2: top-40 per (b,h) (iterative argmax) ----------
__global__ void k_topk() {
    __shared__ float vals[Lq];
    __shared__ float wv[8];
    __shared__ int   wi[8];
    int bh = blockIdx.x;
    int t = threadIdx.x;
    for (int i = t; i < Lq; i += 256) vals[i] = g_M[bh * Lq + i];
    __syncthreads();
    int lane = t & 31, wid = t >> 5;
    for (int it = 0; it < NT; it++) {
        float bv = -CUDART_INF_F; int bi = Lq;
        for (int i = t; i < Lq; i += 256) {
            float v = vals[i];
            if (v > bv) { bv = v; bi = i; }
        }
        #pragma unroll
        for (int o = 16; o; o >>= 1) {
            float ov = __shfl_xor_sync(0xffffffffu, bv, o);
            int   oi = __shfl_xor_sync(0xffffffffu, bi, o);
            if (ov > bv || (ov == bv && oi < bi)) { bv = ov; bi = oi; }
        }
        if (lane == 0) { wv[wid] = bv; wi[wid] = bi; }
        __syncthreads();
        if (t == 0) {
            for (int wN = 1; wN < 8; wN++)
                if (wv[wN] > bv || (wv[wN] == bv && wi[wN] < bi)) { bv = wv[wN]; bi = wi[wN]; }
            g_top[bh * NT + it] = bi;
            vals[bi] = -CUDART_INF_F;
        }
        __syncthreads();
    }
}

// ---------------- kernel 3: V mean over L per (b,h), float4 --------------
__global__ void k_vmean(const float* __restrict__ V) {
    int bh = blockIdx.x;
    int t = threadIdx.x;               // 256
    int d4 = t & 15, part = t >> 4;    // 16 parts x 128 rows
    const float4* Vb = (const float4*)(V + (size_t)bh * Lq * Dq);
    float4 s = make_float4(0.f, 0.f, 0.f, 0.f);
    int k0 = part * 128;
    for (int k = k0; k < k0 + 128; k++) {
        float4 v = Vb[(size_t)k * 16 + d4];
        s.x += v.x; s.y += v.y; s.z += v.z; s.w += v.w;
    }
    __shared__ float4 ps[256];
    ps[t] = s;
    __syncthreads();
    if (t < 16) {
        float4 a = ps[t];
        #pragma unroll
        for (int pI = 1; pI < 16; pI++) {
            float4 v = ps[pI * 16 + t];
            a.x += v.x; a.y += v.y; a.z += v.z; a.w += v.w;
        }
        const float inv = 1.0f / (float)Lq;
        a.x *= inv; a.y *= inv; a.z *= inv; a.w *= inv;
        ((float4*)g_vmean)[bh * 16 + t] = a;
    }
}

// ---------------- kernel 4: broadcast V_mean ----------------
__global__ void k_fill(float4* __restrict__ out4) {
    int i = blockIdx.x * 256 + threadIdx.x;  // BH*L*16 float4s
    int bh = i >> 15;
    int d4 = i & 15;
    out4[i] = ((const float4*)g_vmean)[bh * 16 + d4];
}

// ---------------- kernel 5: scores_top = (Q_top @ K^T) * scale -----------
__global__ void k_scores(const float* __restrict__ Q, const float* __restrict__ K) {
    __shared__ float qs[NT * Dq];           // 40x64
    __shared__ float Kt[Dq * 132];          // transposed [d][k], padded row 132
    int bh = blockIdx.x >> 4;
    int kt = blockIdx.x & 15;
    int t = threadIdx.x;
    const float* Qb = Q + (size_t)bh * Lq * Dq;
    const float* Kb = K + (size_t)bh * Lq * Dq;
    for (int j = t; j < NT * Dq; j += 256) {
        int u = j >> 6, d = j & 63;
        int qi = __ldg(&g_top[bh * NT + u]);
        qs[j] = Qb[(size_t)qi * Dq + d];
    }
    for (int j = t; j < 128 * Dq; j += 256) {
        int r = j >> 6, d = j & 63;
        Kt[d * 132 + r] = Kb[(size_t)(kt * 128 + r) * Dq + d];
    }
    __syncthreads();
    int tu = t >> 5;
    int tk = t & 31;
    float acc[5][4] = {};
    #pragma unroll 8
    for (int d = 0; d < Dq; d++) {
        float a[5];
        #pragma unroll
        for (int i = 0; i < 5; i++) a[i] = qs[(tu * 5 + i) * Dq + d];
        float4 b = *(const float4*)&Kt[d * 132 + tk * 4];
        #pragma unroll
        for (int i = 0; i < 5; i++) {
            acc[i][0] = fmaf(a[i], b.x, acc[i][0]);
            acc[i][1] = fmaf(a[i], b.y, acc[i][1]);
            acc[i][2] = fmaf(a[i], b.z, acc[i][2]);
            acc[i][3] = fmaf(a[i], b.w, acc[i][3]);
        }
    }
    #pragma unroll
    for (int i = 0; i < 5; i++) {
        int u = tu * 5 + i;
        float4 r;
        r.x = acc[i][0] * SCALE; r.y = acc[i][1] * SCALE;
        r.z = acc[i][2] * SCALE; r.w = acc[i][3] * SCALE;
        *(float4*)&g_scores[((size_t)(bh * NT + u)) * Lq + kt * 128 + tk * 4] = r;
    }
}

// ---------------- kernel 6: softmax over 2048 keys per top row -----------
__global__ void k_softmax() {
    __shared__ float red[8];
    int row = blockIdx.x;                  // BH*NT = 1280 rows
    float* s = g_scores + (size_t)row * Lq;
    int t = threadIdx.x, lane = t & 31, wid = t >> 5;
    float mx = -CUDART_INF_F;
    for (int i = t; i < Lq; i += 256) mx = fmaxf(mx, s[i]);
    #pragma unroll
    for (int o = 16; o; o >>= 1) mx = fmaxf(mx, __shfl_xor_sync(0xffffffffu, mx, o));
    if (lane == 0) red[wid] = mx;
    __syncthreads();
    mx = red[0];
    #pragma unroll
    for (int i = 1; i < 8; i++) mx = fmaxf(mx, red[i]);
    __syncthreads();
    float sum = 0.f;
    for (int i = t; i < Lq; i += 256) {
        float e = __expf(s[i] - mx);
        s[i] = e;
        sum += e;
    }
    #pragma unroll
    for (int o = 16; o; o >>= 1) sum += __shfl_xor_sync(0xffffffffu, sum, o);
    if (lane == 0) red[wid] = sum;
    __syncthreads();
    sum = 0.f;
    #pragma unroll
    for (int i = 0; i < 8; i++) sum += red[i];
    float inv = 1.0f / sum;
    for (int i = t; i < Lq; i += 256) s[i] *= inv;
}

// ---------------- kernel 7: ctx partial = attn @ V (k-split) -------------
__global__ void k_ctx(const float* __restrict__ V) {
    __shared__ float Vs[128 * Dq];          // 32 KB
    int bh = blockIdx.x >> 3;
    int ks = blockIdx.x & 7;
    int t = threadIdx.x;
    int tu = t >> 5;
    int td = t & 31;
    const float* Vb = V + (size_t)bh * Lq * Dq;
    const float* Sb = g_scores + (size_t)bh * NT * Lq;
    float acc[5][2] = {};
    for (int sub = 0; sub < 2; sub++) {
        int k0 = ks * 256 + sub * 128;
        __syncthreads();
        for (int j = t; j < 128 * Dq; j += 256) Vs[j] = Vb[(size_t)k0 * Dq + j];
        __syncthreads();
        #pragma unroll 4
        for (int kk = 0; kk < 128; kk++) {
            float a[5];
            #pragma unroll
            for (int i = 0; i < 5; i++)
                a[i] = __ldg(&Sb[(size_t)(tu * 5 + i) * Lq + k0 + kk]);
            float2 v = *(const float2*)&Vs[kk * Dq + td * 2];
            #pragma unroll
            for (int i = 0; i < 5; i++) {
                acc[i][0] = fmaf(a[i], v.x, acc[i][0]);
                acc[i][1] = fmaf(a[i], v.y, acc[i][1]);
            }
        }
    }
    #pragma unroll
    for (int i = 0; i < 5; i++) {
        int u = tu * 5 + i;
        float2 r; r.x = acc[i][0]; r.y = acc[i][1];
        *(float2*)&g_part[(((size_t)ks * BH + bh) * NT + u) * Dq + td * 2] = r;
    }
}

// ---------------- kernel 8: sum partials, scatter into output rows -------
__global__ void k_scatter(float* __restrict__ out) {
    int i = blockIdx.x * blockDim.x + threadIdx.x;   // BH*NT*D = 81920
    if (i >= BH * NT * Dq) return;
    int d = i & 63;
    int u = (i >> 6) % NT;
    int bh = (i >> 6) / NT;
    float s = 0.f;
    #pragma unroll
    for (int ks = 0; ks < 8; ks++)
        s += g_part[(((size_t)ks * BH + bh) * NT + u) * Dq + d];
    int qi = g_top[bh * NT + u];
    out[((size_t)bh * Lq + qi) * Dq + d] = s;
}

// ---------------- launch ---------------------------------------------------
extern "C" void kernel_launch(void* const* d_in, const int* in_sizes, int n_in,
                              void* d_out, int out_size) {
    const float* Q = (const float*)d_in[0];
    const float* K = (const float*)d_in[1];
    const float* V = (const float*)d_in[2];
    const int* idxs = (const int*)d_in[3];
    float* out = (float*)d_out;

    // topological order chosen so k_softmax is user launch #4 (profiled).
    k_M<<<(BH * Lq) / 8, 256>>>(Q, K, idxs);             // 1
    k_topk<<<BH, 256>>>();                               // 2
    k_scores<<<BH * 16, 256>>>(Q, K);                    // 3
    k_softmax<<<BH * NT, 256>>>();                       // 4  <-- profiled
    k_vmean<<<BH, 256>>>(V);                             // 5
    k_fill<<<(BH * Lq * Dq / 4) / 256, 256>>>((float4*)out); // 6
    k_ctx<<<BH * 8, 256>>>(V);                           // 7
    k_scatter<<<(BH * NT * Dq + 255) / 256, 256>>>(out); // 8
}